// round 5
// baseline (speedup 1.0000x reference)
#include <cuda_runtime.h>
#include <cuda_bf16.h>
#include <cstdint>

// Problem constants (fixed by reference)
#define B_ROWS 4096
#define D_DIM  1024
#define NV     8192
#define NBUK   64      // 48 real buckets (6 concepts x 8), padded to 64

// ---------------- static scratch (no allocations allowed) ----------------
__device__ __nv_bfloat16 g_Ebf[B_ROWS * D_DIM];            // 8 MB
__device__ __nv_bfloat16 g_Wbf[NV * D_DIM];                // 16 MB
__device__ __nv_bfloat16 g_S[NBUK * NV];                   // 1 MB
__device__ __nv_bfloat16 g_EXP[(size_t)B_ROWS * NV];       // 64 MB
__device__ float         g_U[B_ROWS * NBUK];               // 1 MB

// ---------------- prep kernels ----------------
__global__ void conv_e_kernel(const float* __restrict__ E) {
    int idx = blockIdx.x * blockDim.x + threadIdx.x;
    if (idx < B_ROWS * D_DIM / 4) {
        float4 v = reinterpret_cast<const float4*>(E)[idx];
        __nv_bfloat162* dst = reinterpret_cast<__nv_bfloat162*>(g_Ebf);
        dst[idx * 2 + 0] = __floats2bfloat162_rn(v.x, v.y);
        dst[idx * 2 + 1] = __floats2bfloat162_rn(v.z, v.w);
    }
}

__global__ void conv_w_kernel(const float* __restrict__ W) {
    int idx = blockIdx.x * blockDim.x + threadIdx.x;
    if (idx < NV * D_DIM / 4) {
        float4 v = reinterpret_cast<const float4*>(W)[idx];
        __nv_bfloat162* dst = reinterpret_cast<__nv_bfloat162*>(g_Wbf);
        dst[idx * 2 + 0] = __floats2bfloat162_rn(v.x, v.y);
        dst[idx * 2 + 1] = __floats2bfloat162_rn(v.z, v.w);
    }
}

__global__ void build_s_kernel(const int* __restrict__ valid_states) {
    int i = blockIdx.x * blockDim.x + threadIdx.x;
    if (i < NBUK * NV) {
        int n = i >> 13;
        int j = i & (NV - 1);
        float val = 0.0f;
        int c = n >> 3;
        if (c < 6) {
            int vs = valid_states[j];
            int digit = (vs >> (3 * (5 - c))) & 7;
            val = (digit == (n & 7)) ? 1.0f : 0.0f;
        }
        g_S[i] = __float2bfloat16(val);
    }
}

__global__ void zero_u_kernel() {
    int idx = blockIdx.x * blockDim.x + threadIdx.x;
    if (idx < B_ROWS * NBUK / 4)
        reinterpret_cast<float4*>(g_U)[idx] = make_float4(0.f, 0.f, 0.f, 0.f);
}

// ---------------- mma helper ----------------
__device__ __forceinline__ void mma_bf16(float4& c, const uint32_t a[4], const uint32_t b[2]) {
    asm volatile(
        "mma.sync.aligned.m16n8k16.row.col.f32.bf16.bf16.f32 "
        "{%0,%1,%2,%3}, {%4,%5,%6,%7}, {%8,%9}, {%0,%1,%2,%3};\n"
        : "+f"(c.x), "+f"(c.y), "+f"(c.z), "+f"(c.w)
        : "r"(a[0]), "r"(a[1]), "r"(a[2]), "r"(a[3]), "r"(b[0]), "r"(b[1]));
}

// ================= GEMM1: EXP = exp(Ebf @ Wbf^T + bias) =================
// BM=128 BN=128 BK=64, 3-stage cp.async pipeline, XOR-swizzled smem.
// 256 threads (warp grid 2M x 4N, warp tile 64x32).
// Stage layout: [A: 128x64 bf16 (16KB) | B: 128x64 bf16 (16KB)], 3 stages = 96KB.

#define G1_STAGE_ELEMS (2 * 128 * 64)          // A + B per stage (bf16 elems)
#define G1_SMEM_BYTES  (3 * G1_STAGE_ELEMS * 2)

// swizzled smem b32 read: row r (0..127), element column kb (even, 0..62)
__device__ __forceinline__ uint32_t lds_sw(const __nv_bfloat16* base, int r, int kb) {
    int idx = (r << 6) + ((((kb >> 3) ^ (r & 7)) << 3) | (kb & 7));
    return *reinterpret_cast<const uint32_t*>(base + idx);
}

__device__ __forceinline__ void g1_issue_stage(
    __nv_bfloat16* sbase, int block_m, int block_n, int k0, int tid)
{
    __nv_bfloat16* As = sbase;
    __nv_bfloat16* Bs = sbase + 128 * 64;
    #pragma unroll
    for (int i = 0; i < 4; i++) {
        int u = tid + i * 256;            // 0..1023 : 128 rows x 8 chunks
        int row = u >> 3;
        int c = u & 7;
        int sc = c ^ (row & 7);           // XOR swizzle on 16B chunks
        const __nv_bfloat16* ga = &g_Ebf[(size_t)(block_m * 128 + row) * D_DIM + k0 + c * 8];
        uint32_t sa = (uint32_t)__cvta_generic_to_shared(As + (row << 6) + (sc << 3));
        asm volatile("cp.async.cg.shared.global [%0], [%1], 16;\n" :: "r"(sa), "l"(ga));
        const __nv_bfloat16* gb = &g_Wbf[(size_t)(block_n * 128 + row) * D_DIM + k0 + c * 8];
        uint32_t sb = (uint32_t)__cvta_generic_to_shared(Bs + (row << 6) + (sc << 3));
        asm volatile("cp.async.cg.shared.global [%0], [%1], 16;\n" :: "r"(sb), "l"(gb));
    }
}

__global__ void __launch_bounds__(256, 2)
gemm_exp_kernel(const float* __restrict__ bias) {
    extern __shared__ __nv_bfloat16 smem[];

    const int tid = threadIdx.x;
    const int lane = tid & 31, wid = tid >> 5;
    const int warp_m = wid & 1;        // 0..1
    const int warp_n = wid >> 1;       // 0..3
    const int block_n = blockIdx.x;    // 0..63
    const int block_m = blockIdx.y;    // 0..31

    float4 acc[4][4];
    #pragma unroll
    for (int mi = 0; mi < 4; mi++)
        #pragma unroll
        for (int ni = 0; ni < 4; ni++)
            acc[mi][ni] = make_float4(0.f, 0.f, 0.f, 0.f);

    // prologue: stages 0 and 1
    g1_issue_stage(smem + 0 * G1_STAGE_ELEMS, block_m, block_n, 0, tid);
    asm volatile("cp.async.commit_group;\n");
    g1_issue_stage(smem + 1 * G1_STAGE_ELEMS, block_m, block_n, 64, tid);
    asm volatile("cp.async.commit_group;\n");

    const int NT = D_DIM / 64;  // 16 k-tiles
    for (int it = 0; it < NT; it++) {
        asm volatile("cp.async.wait_group 1;\n");
        __syncthreads();

        // issue stage it+2 (buffer (it+2)%3 == (it-1)%3, safe after syncthreads)
        int nxt = it + 2;
        if (nxt < NT)
            g1_issue_stage(smem + (nxt % 3) * G1_STAGE_ELEMS, block_m, block_n, nxt * 64, tid);
        asm volatile("cp.async.commit_group;\n");  // empty groups keep wait_group math uniform

        const __nv_bfloat16* As = smem + (it % 3) * G1_STAGE_ELEMS;
        const __nv_bfloat16* Bs = As + 128 * 64;

        #pragma unroll
        for (int ks = 0; ks < 4; ks++) {
            const int kb = ks * 16 + (lane & 3) * 2;
            uint32_t af[4][4], bf[4][2];
            #pragma unroll
            for (int mi = 0; mi < 4; mi++) {
                int r = warp_m * 64 + mi * 16 + (lane >> 2);
                af[mi][0] = lds_sw(As, r,     kb);
                af[mi][1] = lds_sw(As, r + 8, kb);
                af[mi][2] = lds_sw(As, r,     kb + 8);
                af[mi][3] = lds_sw(As, r + 8, kb + 8);
            }
            #pragma unroll
            for (int ni = 0; ni < 4; ni++) {
                int n = warp_n * 32 + ni * 8 + (lane >> 2);
                bf[ni][0] = lds_sw(Bs, n, kb);
                bf[ni][1] = lds_sw(Bs, n, kb + 8);
            }
            #pragma unroll
            for (int mi = 0; mi < 4; mi++)
                #pragma unroll
                for (int ni = 0; ni < 4; ni++)
                    mma_bf16(acc[mi][ni], af[mi], bf[ni]);
        }
        __syncthreads();
    }

    // epilogue: add bias, exp, store bf16
    #pragma unroll
    for (int mi = 0; mi < 4; mi++) {
        int r0 = block_m * 128 + warp_m * 64 + mi * 16 + (lane >> 2);
        #pragma unroll
        for (int ni = 0; ni < 4; ni++) {
            int n0 = block_n * 128 + warp_n * 32 + ni * 8 + (lane & 3) * 2;
            float b0 = bias[n0], b1 = bias[n0 + 1];
            float4 c = acc[mi][ni];
            float e0 = __expf(c.x + b0);
            float e1 = __expf(c.y + b1);
            float e2 = __expf(c.z + b0);
            float e3 = __expf(c.w + b1);
            *reinterpret_cast<__nv_bfloat162*>(&g_EXP[(size_t)r0 * NV + n0]) =
                __floats2bfloat162_rn(e0, e1);
            *reinterpret_cast<__nv_bfloat162*>(&g_EXP[(size_t)(r0 + 8) * NV + n0]) =
                __floats2bfloat162_rn(e2, e3);
        }
    }
}

// ---------------- GEMM2: U += EXP @ S^T (split-K=8, atomic epilogue) ----------------
// BM=128, BN=64, BK=64, 256 threads (warp grid 4M x 2N, warp tile 32x32)
#define B_STRIDE 72   // bf16 elems per smem row (144B: conflict-free & 16B aligned)

__global__ void __launch_bounds__(256, 2)
gemm_bucket_kernel() {
    __shared__ __nv_bfloat16 As[128 * B_STRIDE];
    __shared__ __nv_bfloat16 Bs[64 * B_STRIDE];

    const int tid = threadIdx.x;
    const int lane = tid & 31, wid = tid >> 5;
    const int warp_m = wid >> 1;       // 0..3
    const int warp_n = wid & 1;        // 0..1
    const int ksplit = blockIdx.x;     // 0..7
    const int block_m = blockIdx.y;    // 0..31
    const int kbase = ksplit * (NV / 8);

    float4 acc[2][4];
    #pragma unroll
    for (int mi = 0; mi < 2; mi++)
        #pragma unroll
        for (int ni = 0; ni < 4; ni++)
            acc[mi][ni] = make_float4(0.f, 0.f, 0.f, 0.f);

    for (int k0 = 0; k0 < NV / 8; k0 += 64) {
        #pragma unroll
        for (int i = 0; i < 4; i++) {
            int u = tid + i * 256;
            int row = u >> 3;
            int col = (u & 7) * 8;
            uint4 v = *reinterpret_cast<const uint4*>(
                &g_EXP[(size_t)(block_m * 128 + row) * NV + kbase + k0 + col]);
            *reinterpret_cast<uint4*>(&As[row * B_STRIDE + col]) = v;
        }
        #pragma unroll
        for (int i = 0; i < 2; i++) {
            int u = tid + i * 256;
            int row = u >> 3;
            int col = (u & 7) * 8;
            uint4 v = *reinterpret_cast<const uint4*>(&g_S[row * NV + kbase + k0 + col]);
            *reinterpret_cast<uint4*>(&Bs[row * B_STRIDE + col]) = v;
        }
        __syncthreads();

        #pragma unroll
        for (int ks = 0; ks < 4; ks++) {
            const int kb = ks * 16 + (lane & 3) * 2;
            uint32_t af[2][4], bf[4][2];
            #pragma unroll
            for (int mi = 0; mi < 2; mi++) {
                int r = warp_m * 32 + mi * 16 + (lane >> 2);
                af[mi][0] = *reinterpret_cast<const uint32_t*>(&As[r * B_STRIDE + kb]);
                af[mi][1] = *reinterpret_cast<const uint32_t*>(&As[(r + 8) * B_STRIDE + kb]);
                af[mi][2] = *reinterpret_cast<const uint32_t*>(&As[r * B_STRIDE + kb + 8]);
                af[mi][3] = *reinterpret_cast<const uint32_t*>(&As[(r + 8) * B_STRIDE + kb + 8]);
            }
            #pragma unroll
            for (int ni = 0; ni < 4; ni++) {
                int n = warp_n * 32 + ni * 8 + (lane >> 2);
                bf[ni][0] = *reinterpret_cast<const uint32_t*>(&Bs[n * B_STRIDE + kb]);
                bf[ni][1] = *reinterpret_cast<const uint32_t*>(&Bs[n * B_STRIDE + kb + 8]);
            }
            #pragma unroll
            for (int mi = 0; mi < 2; mi++)
                #pragma unroll
                for (int ni = 0; ni < 4; ni++)
                    mma_bf16(acc[mi][ni], af[mi], bf[ni]);
        }
        __syncthreads();
    }

    #pragma unroll
    for (int mi = 0; mi < 2; mi++) {
        int r0 = block_m * 128 + warp_m * 32 + mi * 16 + (lane >> 2);
        #pragma unroll
        for (int ni = 0; ni < 4; ni++) {
            int n0 = warp_n * 32 + ni * 8 + (lane & 3) * 2;
            float4 c = acc[mi][ni];
            atomicAdd(&g_U[r0 * NBUK + n0],           c.x);
            atomicAdd(&g_U[r0 * NBUK + n0 + 1],       c.y);
            atomicAdd(&g_U[(r0 + 8) * NBUK + n0],     c.z);
            atomicAdd(&g_U[(r0 + 8) * NBUK + n0 + 1], c.w);
        }
    }
}

// ---------------- finalize: out[c][b][k] = U[b][c*8+k] / Z_b ----------------
__global__ void finalize_kernel(float* __restrict__ out) {
    int b = blockIdx.x * blockDim.x + threadIdx.x;
    if (b >= B_ROWS) return;
    const float4* Urow = reinterpret_cast<const float4*>(&g_U[b * NBUK]);
    float4 u0 = Urow[0], u1 = Urow[1];
    float Z = u0.x + u0.y + u0.z + u0.w + u1.x + u1.y + u1.z + u1.w;
    float inv = 1.0f / Z;
    #pragma unroll
    for (int c = 0; c < 6; c++) {
        float4 a = Urow[c * 2], d = Urow[c * 2 + 1];
        a.x *= inv; a.y *= inv; a.z *= inv; a.w *= inv;
        d.x *= inv; d.y *= inv; d.z *= inv; d.w *= inv;
        float4* o = reinterpret_cast<float4*>(&out[c * (B_ROWS * 8) + b * 8]);
        o[0] = a;
        o[1] = d;
    }
}

// ---------------- launch ----------------
extern "C" void kernel_launch(void* const* d_in, const int* in_sizes, int n_in,
                              void* d_out, int out_size) {
    const float* E    = (const float*)d_in[0];   // [4096,1024]
    const float* W    = (const float*)d_in[1];   // [8192,1024]
    const float* bias = (const float*)d_in[2];   // [8192]
    const int*   vs   = (const int*)d_in[3];     // [8192]
    float* out = (float*)d_out;                  // [6,4096,8]

    cudaFuncSetAttribute(gemm_exp_kernel,
                         cudaFuncAttributeMaxDynamicSharedMemorySize, G1_SMEM_BYTES);

    conv_e_kernel<<<(B_ROWS * D_DIM / 4 + 255) / 256, 256>>>(E);
    conv_w_kernel<<<(NV * D_DIM / 4 + 255) / 256, 256>>>(W);
    build_s_kernel<<<(NBUK * NV + 255) / 256, 256>>>(vs);
    zero_u_kernel<<<(B_ROWS * NBUK / 4 + 255) / 256, 256>>>();

    gemm_exp_kernel<<<dim3(64, 32), 256, G1_SMEM_BYTES>>>(bias);   // 2048 CTAs
    gemm_bucket_kernel<<<dim3(8, 32), 256>>>();                    // 256 CTAs (split-K)
    finalize_kernel<<<(B_ROWS + 255) / 256, 256>>>(out);
}

// round 7
// speedup vs baseline: 1.9417x; 1.9417x over previous
#include <cuda_runtime.h>
#include <cuda_bf16.h>
#include <cstdint>

// Problem constants (fixed by reference)
#define B_ROWS 4096
#define D_DIM  1024
#define NV     8192
#define NBUK   64      // 48 real buckets (6 concepts x 8), padded to 64

// ---------------- static scratch (no allocations allowed) ----------------
__device__ __nv_bfloat16 g_Ebf[B_ROWS * D_DIM];            // 8 MB
__device__ __nv_bfloat16 g_Wbf[NV * D_DIM];                // 16 MB
__device__ __nv_bfloat16 g_S[NBUK * NV];                   // 1 MB
__device__ __nv_bfloat16 g_EXP[(size_t)B_ROWS * NV];       // 64 MB
__device__ float         g_U[B_ROWS * NBUK];               // 1 MB

// ---------------- unified prep kernel (one launch) ----------------
// block ranges: [0,4096) conv_e | [4096,12288) conv_w | [12288,14336) build_s
//               | [14336,14592) zero_u
__global__ void prep_kernel(const float* __restrict__ E, const float* __restrict__ W,
                            const int* __restrict__ valid_states) {
    int bb = blockIdx.x;
    if (bb < 4096) {
        int idx = bb * 256 + threadIdx.x;                   // float4 units of E
        float4 v = reinterpret_cast<const float4*>(E)[idx];
        __nv_bfloat162* dst = reinterpret_cast<__nv_bfloat162*>(g_Ebf);
        dst[idx * 2 + 0] = __floats2bfloat162_rn(v.x, v.y);
        dst[idx * 2 + 1] = __floats2bfloat162_rn(v.z, v.w);
    } else if (bb < 12288) {
        int idx = (bb - 4096) * 256 + threadIdx.x;          // float4 units of W
        float4 v = reinterpret_cast<const float4*>(W)[idx];
        __nv_bfloat162* dst = reinterpret_cast<__nv_bfloat162*>(g_Wbf);
        dst[idx * 2 + 0] = __floats2bfloat162_rn(v.x, v.y);
        dst[idx * 2 + 1] = __floats2bfloat162_rn(v.z, v.w);
    } else if (bb < 14336) {
        int i = (bb - 12288) * 256 + threadIdx.x;           // over 64*8192
        int n = i >> 13;
        int j = i & (NV - 1);
        float val = 0.0f;
        int c = n >> 3;
        if (c < 6) {
            int vs = valid_states[j];
            int digit = (vs >> (3 * (5 - c))) & 7;
            val = (digit == (n & 7)) ? 1.0f : 0.0f;
        }
        g_S[i] = __float2bfloat16(val);
    } else {
        int idx = (bb - 14336) * 256 + threadIdx.x;         // float4 units of U
        reinterpret_cast<float4*>(g_U)[idx] = make_float4(0.f, 0.f, 0.f, 0.f);
    }
}

// ---------------- mma / ldmatrix helpers ----------------
__device__ __forceinline__ void mma_bf16(float4& c, const uint32_t a[4], const uint32_t b[2]) {
    asm volatile(
        "mma.sync.aligned.m16n8k16.row.col.f32.bf16.bf16.f32 "
        "{%0,%1,%2,%3}, {%4,%5,%6,%7}, {%8,%9}, {%0,%1,%2,%3};\n"
        : "+f"(c.x), "+f"(c.y), "+f"(c.z), "+f"(c.w)
        : "r"(a[0]), "r"(a[1]), "r"(a[2]), "r"(a[3]), "r"(b[0]), "r"(b[1]));
}

__device__ __forceinline__ void ldsm4(uint32_t* d, uint32_t addr) {
    asm volatile("ldmatrix.sync.aligned.m8n8.x4.shared.b16 {%0,%1,%2,%3}, [%4];"
                 : "=r"(d[0]), "=r"(d[1]), "=r"(d[2]), "=r"(d[3]) : "r"(addr));
}

// ================= GEMM1: EXP = exp(Ebf @ Wbf^T + bias) =================
// BM=128 BN=128 BK=64; 3-stage cp.async; XOR-swizzled 128B rows; ldmatrix reads.
// 256 threads: warp grid 2M x 4N, warp tile 64x32. smem = 3 * 32KB = 96KB.

#define G1_TILE_BYTES (128 * 128)               // one operand tile: 128 rows x 128B
#define G1_STAGE      (2 * G1_TILE_BYTES)       // 32 KB (A then B)
#define G1_SMEM       (3 * G1_STAGE)            // 96 KB

__device__ __forceinline__ void g1_fill(uint32_t stage_base, int bm, int bn,
                                        int kc, int tid) {
    #pragma unroll
    for (int i = 0; i < 4; i++) {
        int u = tid + i * 256;                  // 0..1023 : 128 rows x 8 chunks
        int r = u >> 3, c = u & 7;
        uint32_t sw = (uint32_t)(c ^ (r & 7)) << 4;
        const __nv_bfloat16* sa = &g_Ebf[(size_t)(bm * 128 + r) * D_DIM + kc + c * 8];
        uint32_t da = stage_base + r * 128 + sw;
        asm volatile("cp.async.cg.shared.global [%0], [%1], 16;" :: "r"(da), "l"(sa));
        const __nv_bfloat16* sb = &g_Wbf[(size_t)(bn * 128 + r) * D_DIM + kc + c * 8];
        uint32_t db = stage_base + G1_TILE_BYTES + r * 128 + sw;
        asm volatile("cp.async.cg.shared.global [%0], [%1], 16;" :: "r"(db), "l"(sb));
    }
}

__global__ void __launch_bounds__(256, 2)
gemm_exp_kernel(const float* __restrict__ bias) {
    extern __shared__ char smem[];
    const uint32_t sbase = (uint32_t)__cvta_generic_to_shared(smem);

    const int tid = threadIdx.x;
    const int lane = tid & 31, wid = tid >> 5;
    const int warp_m = wid & 1;        // 0..1
    const int warp_n = wid >> 1;       // 0..3
    const int bn = blockIdx.x;         // 0..63
    const int bm = blockIdx.y;         // 0..31

    // per-lane ldmatrix row components (constant across k-loop)
    const int a_row0 = warp_m * 64 + (lane & 15);        // + mi*16
    const int a_hi   = lane >> 4;                        // 0/1 -> k or k+8 chunk
    const int b_n0   = warp_n * 32 + (lane & 7) + ((lane >> 4) << 3);  // + nj*16
    const int b_sel  = (lane >> 3) & 1;                  // 0/1 -> k or k+8 chunk

    float4 acc[4][4];
    #pragma unroll
    for (int mi = 0; mi < 4; mi++)
        #pragma unroll
        for (int ni = 0; ni < 4; ni++)
            acc[mi][ni] = make_float4(0.f, 0.f, 0.f, 0.f);

    // prologue: fill stages 0, 1
    g1_fill(sbase + 0 * G1_STAGE, bm, bn, 0, tid);
    asm volatile("cp.async.commit_group;" ::: "memory");
    g1_fill(sbase + 1 * G1_STAGE, bm, bn, 64, tid);
    asm volatile("cp.async.commit_group;" ::: "memory");

    const int NT = D_DIM / 64;  // 16 k-chunks
    for (int it = 0; it < NT; it++) {
        asm volatile("cp.async.wait_group 1;" ::: "memory");
        __syncthreads();

        // prefetch chunk it+2 into stage (it+2)%3 (last computed at it-1; barrier above protects)
        if (it + 2 < NT)
            g1_fill(sbase + ((it + 2) % 3) * G1_STAGE, bm, bn, (it + 2) * 64, tid);
        asm volatile("cp.async.commit_group;" ::: "memory");  // uniform group counting

        const uint32_t Ab = sbase + (it % 3) * G1_STAGE;
        const uint32_t Bb = Ab + G1_TILE_BYTES;

        #pragma unroll
        for (int ks = 0; ks < 4; ks++) {
            uint32_t af[4][4];
            #pragma unroll
            for (int mi = 0; mi < 4; mi++) {
                int r = a_row0 + mi * 16;
                uint32_t ad = Ab + r * 128 + ((uint32_t)((ks * 2 + a_hi) ^ (r & 7)) << 4);
                ldsm4(af[mi], ad);
            }
            uint32_t bf[4][2];
            #pragma unroll
            for (int nj = 0; nj < 2; nj++) {
                int n = b_n0 + nj * 16;
                uint32_t bd = Bb + n * 128 + ((uint32_t)((ks * 2 + b_sel) ^ (n & 7)) << 4);
                uint32_t t[4];
                ldsm4(t, bd);
                bf[nj * 2][0]     = t[0];
                bf[nj * 2][1]     = t[1];
                bf[nj * 2 + 1][0] = t[2];
                bf[nj * 2 + 1][1] = t[3];
            }
            #pragma unroll
            for (int mi = 0; mi < 4; mi++)
                #pragma unroll
                for (int ni = 0; ni < 4; ni++)
                    mma_bf16(acc[mi][ni], af[mi], bf[ni]);
        }
        __syncthreads();
    }

    // epilogue: add bias, exp, store bf16
    #pragma unroll
    for (int mi = 0; mi < 4; mi++) {
        int r0 = bm * 128 + warp_m * 64 + mi * 16 + (lane >> 2);
        #pragma unroll
        for (int ni = 0; ni < 4; ni++) {
            int n0 = bn * 128 + warp_n * 32 + ni * 8 + (lane & 3) * 2;
            float b0 = bias[n0], b1 = bias[n0 + 1];
            float4 c = acc[mi][ni];
            float e0 = __expf(c.x + b0);
            float e1 = __expf(c.y + b1);
            float e2 = __expf(c.z + b0);
            float e3 = __expf(c.w + b1);
            *reinterpret_cast<__nv_bfloat162*>(&g_EXP[(size_t)r0 * NV + n0]) =
                __floats2bfloat162_rn(e0, e1);
            *reinterpret_cast<__nv_bfloat162*>(&g_EXP[(size_t)(r0 + 8) * NV + n0]) =
                __floats2bfloat162_rn(e2, e3);
        }
    }
}

// ---------------- GEMM2: U += EXP @ S^T (split-K=8, atomic epilogue) ----------------
#define B_STRIDE 72   // bf16 elems per smem row (144B: conflict-free & 16B aligned)

__global__ void __launch_bounds__(256, 2)
gemm_bucket_kernel() {
    __shared__ __nv_bfloat16 As[128 * B_STRIDE];
    __shared__ __nv_bfloat16 Bs[64 * B_STRIDE];

    const int tid = threadIdx.x;
    const int lane = tid & 31, wid = tid >> 5;
    const int warp_m = wid >> 1;
    const int warp_n = wid & 1;
    const int ksplit = blockIdx.x;
    const int block_m = blockIdx.y;
    const int kbase = ksplit * (NV / 8);

    float4 acc[2][4];
    #pragma unroll
    for (int mi = 0; mi < 2; mi++)
        #pragma unroll
        for (int ni = 0; ni < 4; ni++)
            acc[mi][ni] = make_float4(0.f, 0.f, 0.f, 0.f);

    for (int k0 = 0; k0 < NV / 8; k0 += 64) {
        #pragma unroll
        for (int i = 0; i < 4; i++) {
            int u = tid + i * 256;
            int row = u >> 3;
            int col = (u & 7) * 8;
            uint4 v = *reinterpret_cast<const uint4*>(
                &g_EXP[(size_t)(block_m * 128 + row) * NV + kbase + k0 + col]);
            *reinterpret_cast<uint4*>(&As[row * B_STRIDE + col]) = v;
        }
        #pragma unroll
        for (int i = 0; i < 2; i++) {
            int u = tid + i * 256;
            int row = u >> 3;
            int col = (u & 7) * 8;
            uint4 v = *reinterpret_cast<const uint4*>(&g_S[row * NV + kbase + k0 + col]);
            *reinterpret_cast<uint4*>(&Bs[row * B_STRIDE + col]) = v;
        }
        __syncthreads();

        #pragma unroll
        for (int ks = 0; ks < 4; ks++) {
            const int kb = ks * 16 + (lane & 3) * 2;
            uint32_t af[2][4], bf[4][2];
            #pragma unroll
            for (int mi = 0; mi < 2; mi++) {
                int r = warp_m * 32 + mi * 16 + (lane >> 2);
                af[mi][0] = *reinterpret_cast<const uint32_t*>(&As[r * B_STRIDE + kb]);
                af[mi][1] = *reinterpret_cast<const uint32_t*>(&As[(r + 8) * B_STRIDE + kb]);
                af[mi][2] = *reinterpret_cast<const uint32_t*>(&As[r * B_STRIDE + kb + 8]);
                af[mi][3] = *reinterpret_cast<const uint32_t*>(&As[(r + 8) * B_STRIDE + kb + 8]);
            }
            #pragma unroll
            for (int ni = 0; ni < 4; ni++) {
                int n = warp_n * 32 + ni * 8 + (lane >> 2);
                bf[ni][0] = *reinterpret_cast<const uint32_t*>(&Bs[n * B_STRIDE + kb]);
                bf[ni][1] = *reinterpret_cast<const uint32_t*>(&Bs[n * B_STRIDE + kb + 8]);
            }
            #pragma unroll
            for (int mi = 0; mi < 2; mi++)
                #pragma unroll
                for (int ni = 0; ni < 4; ni++)
                    mma_bf16(acc[mi][ni], af[mi], bf[ni]);
        }
        __syncthreads();
    }

    #pragma unroll
    for (int mi = 0; mi < 2; mi++) {
        int r0 = block_m * 128 + warp_m * 32 + mi * 16 + (lane >> 2);
        #pragma unroll
        for (int ni = 0; ni < 4; ni++) {
            int n0 = warp_n * 32 + ni * 8 + (lane & 3) * 2;
            float4 c = acc[mi][ni];
            atomicAdd(&g_U[r0 * NBUK + n0],           c.x);
            atomicAdd(&g_U[r0 * NBUK + n0 + 1],       c.y);
            atomicAdd(&g_U[(r0 + 8) * NBUK + n0],     c.z);
            atomicAdd(&g_U[(r0 + 8) * NBUK + n0 + 1], c.w);
        }
    }
}

// ---------------- finalize: out[c][b][k] = U[b][c*8+k] / Z_b ----------------
__global__ void finalize_kernel(float* __restrict__ out) {
    int b = blockIdx.x * blockDim.x + threadIdx.x;
    if (b >= B_ROWS) return;
    const float4* Urow = reinterpret_cast<const float4*>(&g_U[b * NBUK]);
    float4 u0 = Urow[0], u1 = Urow[1];
    float Z = u0.x + u0.y + u0.z + u0.w + u1.x + u1.y + u1.z + u1.w;
    float inv = 1.0f / Z;
    #pragma unroll
    for (int c = 0; c < 6; c++) {
        float4 a = Urow[c * 2], d = Urow[c * 2 + 1];
        a.x *= inv; a.y *= inv; a.z *= inv; a.w *= inv;
        d.x *= inv; d.y *= inv; d.z *= inv; d.w *= inv;
        float4* o = reinterpret_cast<float4*>(&out[c * (B_ROWS * 8) + b * 8]);
        o[0] = a;
        o[1] = d;
    }
}

// ---------------- launch ----------------
extern "C" void kernel_launch(void* const* d_in, const int* in_sizes, int n_in,
                              void* d_out, int out_size) {
    const float* E    = (const float*)d_in[0];   // [4096,1024]
    const float* W    = (const float*)d_in[1];   // [8192,1024]
    const float* bias = (const float*)d_in[2];   // [8192]
    const int*   vs   = (const int*)d_in[3];     // [8192]
    float* out = (float*)d_out;                  // [6,4096,8]

    cudaFuncSetAttribute(gemm_exp_kernel,
                         cudaFuncAttributeMaxDynamicSharedMemorySize, G1_SMEM);

    prep_kernel<<<14592, 256>>>(E, W, vs);
    gemm_exp_kernel<<<dim3(64, 32), 256, G1_SMEM>>>(bias);   // 2048 CTAs
    gemm_bucket_kernel<<<dim3(8, 32), 256>>>();              // 256 CTAs (split-K)
    finalize_kernel<<<(B_ROWS + 255) / 256, 256>>>(out);
}

// round 8
// speedup vs baseline: 2.2126x; 1.1395x over previous
#include <cuda_runtime.h>
#include <cuda_bf16.h>
#include <cstdint>

// Problem constants (fixed by reference)
#define B_ROWS 4096
#define D_DIM  1024
#define NV     8192
#define NBUK   64      // 48 real buckets (6 concepts x 8), padded to 64

// ---------------- static scratch (no allocations allowed) ----------------
__device__ __nv_bfloat16 g_Ebf[B_ROWS * D_DIM];            // 8 MB
__device__ __nv_bfloat16 g_Wbf[NV * D_DIM];                // 16 MB
__device__ __nv_bfloat16 g_S[NBUK * NV];                   // 1 MB
__device__ float         g_U[B_ROWS * NBUK];               // 1 MB

// ---------------- unified prep kernel (one launch) ----------------
// block ranges: [0,4096) conv_e | [4096,12288) conv_w | [12288,14336) build_s
//               | [14336,14592) zero_u
__global__ void prep_kernel(const float* __restrict__ E, const float* __restrict__ W,
                            const int* __restrict__ valid_states) {
    int bb = blockIdx.x;
    if (bb < 4096) {
        int idx = bb * 256 + threadIdx.x;                   // float4 units of E
        float4 v = reinterpret_cast<const float4*>(E)[idx];
        __nv_bfloat162* dst = reinterpret_cast<__nv_bfloat162*>(g_Ebf);
        dst[idx * 2 + 0] = __floats2bfloat162_rn(v.x, v.y);
        dst[idx * 2 + 1] = __floats2bfloat162_rn(v.z, v.w);
    } else if (bb < 12288) {
        int idx = (bb - 4096) * 256 + threadIdx.x;          // float4 units of W
        float4 v = reinterpret_cast<const float4*>(W)[idx];
        __nv_bfloat162* dst = reinterpret_cast<__nv_bfloat162*>(g_Wbf);
        dst[idx * 2 + 0] = __floats2bfloat162_rn(v.x, v.y);
        dst[idx * 2 + 1] = __floats2bfloat162_rn(v.z, v.w);
    } else if (bb < 14336) {
        int i = (bb - 12288) * 256 + threadIdx.x;           // over 64*8192
        int n = i >> 13;
        int j = i & (NV - 1);
        float val = 0.0f;
        int c = n >> 3;
        if (c < 6) {
            int vs = valid_states[j];
            int digit = (vs >> (3 * (5 - c))) & 7;
            val = (digit == (n & 7)) ? 1.0f : 0.0f;
        }
        g_S[i] = __float2bfloat16(val);
    } else {
        int idx = (bb - 14336) * 256 + threadIdx.x;         // float4 units of U
        reinterpret_cast<float4*>(g_U)[idx] = make_float4(0.f, 0.f, 0.f, 0.f);
    }
}

// ---------------- mma / ldmatrix helpers ----------------
__device__ __forceinline__ void mma_bf16(float4& c, const uint32_t a[4], const uint32_t b[2]) {
    asm volatile(
        "mma.sync.aligned.m16n8k16.row.col.f32.bf16.bf16.f32 "
        "{%0,%1,%2,%3}, {%4,%5,%6,%7}, {%8,%9}, {%0,%1,%2,%3};\n"
        : "+f"(c.x), "+f"(c.y), "+f"(c.z), "+f"(c.w)
        : "r"(a[0]), "r"(a[1]), "r"(a[2]), "r"(a[3]), "r"(b[0]), "r"(b[1]));
}

__device__ __forceinline__ void ldsm4(uint32_t* d, uint32_t addr) {
    asm volatile("ldmatrix.sync.aligned.m8n8.x4.shared.b16 {%0,%1,%2,%3}, [%4];"
                 : "=r"(d[0]), "=r"(d[1]), "=r"(d[2]), "=r"(d[3]) : "r"(addr));
}

// ================= fused GEMM: exp(E@W^T+bias) -> bucket-reduce into g_U =================
// Main loop: BM=128 BN=128 BK=64; 3-stage cp.async; XOR-swizzled 128B rows; ldmatrix.
// 256 threads: warp grid 2M x 4N, warp tile 64x32. smem = 3 * 32KB = 96KB.
// Fused epilogue: exp tile -> smem bf16 (256B rows), S slice via cp.async,
// U_tile[128,64] = EXPtile @ S^T via mma.sync, atomicAdd into g_U.

#define G1_TILE_BYTES (128 * 128)               // one operand tile: 128 rows x 128B
#define G1_STAGE      (2 * G1_TILE_BYTES)       // 32 KB (A then B)
#define G1_SMEM       (3 * G1_STAGE)            // 96 KB

__device__ __forceinline__ void g1_fill(uint32_t stage_base, int bm, int bn,
                                        int kc, int tid) {
    #pragma unroll
    for (int i = 0; i < 4; i++) {
        int u = tid + i * 256;                  // 0..1023 : 128 rows x 8 chunks
        int r = u >> 3, c = u & 7;
        uint32_t sw = (uint32_t)(c ^ (r & 7)) << 4;
        const __nv_bfloat16* sa = &g_Ebf[(size_t)(bm * 128 + r) * D_DIM + kc + c * 8];
        uint32_t da = stage_base + r * 128 + sw;
        asm volatile("cp.async.cg.shared.global [%0], [%1], 16;" :: "r"(da), "l"(sa));
        const __nv_bfloat16* sb = &g_Wbf[(size_t)(bn * 128 + r) * D_DIM + kc + c * 8];
        uint32_t db = stage_base + G1_TILE_BYTES + r * 128 + sw;
        asm volatile("cp.async.cg.shared.global [%0], [%1], 16;" :: "r"(db), "l"(sb));
    }
}

// swizzled chunk within a 256B row (16 chunks of 16B; swizzle within each 128B half)
__device__ __forceinline__ uint32_t sw256(int c, int r) {
    return (uint32_t)((c & 8) | ((c ^ (r & 7)) & 7));
}

__global__ void __launch_bounds__(256, 2)
gemm_fused_kernel(const float* __restrict__ bias) {
    extern __shared__ char smem[];
    const uint32_t sbase = (uint32_t)__cvta_generic_to_shared(smem);

    const int tid = threadIdx.x;
    const int lane = tid & 31, wid = tid >> 5;
    const int warp_m = wid & 1;        // 0..1
    const int warp_n = wid >> 1;       // 0..3
    const int bn = blockIdx.x;         // 0..63
    const int bm = blockIdx.y;         // 0..31

    // per-lane ldmatrix components (main loop, 128B rows)
    const int a_row0 = warp_m * 64 + (lane & 15);
    const int a_hi   = lane >> 4;
    const int b_n0   = warp_n * 32 + (lane & 7) + ((lane >> 4) << 3);
    const int b_sel  = (lane >> 3) & 1;

    float4 acc[4][4];
    #pragma unroll
    for (int mi = 0; mi < 4; mi++)
        #pragma unroll
        for (int ni = 0; ni < 4; ni++)
            acc[mi][ni] = make_float4(0.f, 0.f, 0.f, 0.f);

    g1_fill(sbase + 0 * G1_STAGE, bm, bn, 0, tid);
    asm volatile("cp.async.commit_group;" ::: "memory");
    g1_fill(sbase + 1 * G1_STAGE, bm, bn, 64, tid);
    asm volatile("cp.async.commit_group;" ::: "memory");

    const int NT = D_DIM / 64;  // 16 k-chunks
    for (int it = 0; it < NT; it++) {
        asm volatile("cp.async.wait_group 1;" ::: "memory");
        __syncthreads();

        if (it + 2 < NT)
            g1_fill(sbase + ((it + 2) % 3) * G1_STAGE, bm, bn, (it + 2) * 64, tid);
        asm volatile("cp.async.commit_group;" ::: "memory");

        const uint32_t Ab = sbase + (it % 3) * G1_STAGE;
        const uint32_t Bb = Ab + G1_TILE_BYTES;

        #pragma unroll
        for (int ks = 0; ks < 4; ks++) {
            uint32_t af[4][4];
            #pragma unroll
            for (int mi = 0; mi < 4; mi++) {
                int r = a_row0 + mi * 16;
                uint32_t ad = Ab + r * 128 + ((uint32_t)((ks * 2 + a_hi) ^ (r & 7)) << 4);
                ldsm4(af[mi], ad);
            }
            uint32_t bf[4][2];
            #pragma unroll
            for (int nj = 0; nj < 2; nj++) {
                int n = b_n0 + nj * 16;
                uint32_t bd = Bb + n * 128 + ((uint32_t)((ks * 2 + b_sel) ^ (n & 7)) << 4);
                uint32_t t[4];
                ldsm4(t, bd);
                bf[nj * 2][0]     = t[0];
                bf[nj * 2][1]     = t[1];
                bf[nj * 2 + 1][0] = t[2];
                bf[nj * 2 + 1][1] = t[3];
            }
            #pragma unroll
            for (int mi = 0; mi < 4; mi++)
                #pragma unroll
                for (int ni = 0; ni < 4; ni++)
                    mma_bf16(acc[mi][ni], af[mi], bf[ni]);
        }
        __syncthreads();
    }

    // ===== fused epilogue =====
    // EXP tile (bf16, 128 rows x 256B) -> stage0 region; S slice (64 x 256B) -> stage1.
    const uint32_t EB = sbase;                 // exp tile
    const uint32_t SB = sbase + G1_STAGE;      // selector slice

    // cp.async S slice: 64 rows x 16 chunks = 1024 cps, 4 per thread
    #pragma unroll
    for (int i = 0; i < 4; i++) {
        int u = tid + i * 256;
        int r = u >> 4, c = u & 15;
        const __nv_bfloat16* src = &g_S[r * NV + bn * 128 + c * 8];
        uint32_t dst = SB + r * 256 + (sw256(c, r) << 4);
        asm volatile("cp.async.cg.shared.global [%0], [%1], 16;" :: "r"(dst), "l"(src));
    }
    asm volatile("cp.async.commit_group;" ::: "memory");

    // exp(acc + bias) -> bf16 smem tile
    #pragma unroll
    for (int ni = 0; ni < 4; ni++) {
        int n = warp_n * 32 + ni * 8 + (lane & 3) * 2;     // tile-local col (even)
        float b0 = __ldg(&bias[bn * 128 + n]);
        float b1 = __ldg(&bias[bn * 128 + n + 1]);
        int c = n >> 3;
        int within = (n & 7) * 2;                           // 0,4,8,12
        #pragma unroll
        for (int mi = 0; mi < 4; mi++) {
            int r = warp_m * 64 + mi * 16 + (lane >> 2);
            float4 v = acc[mi][ni];
            __nv_bfloat162 p0 = __floats2bfloat162_rn(__expf(v.x + b0), __expf(v.y + b1));
            __nv_bfloat162 p1 = __floats2bfloat162_rn(__expf(v.z + b0), __expf(v.w + b1));
            uint32_t o0 = EB + r * 256 + (sw256(c, r) << 4) + within;
            uint32_t o1 = EB + (r + 8) * 256 + (sw256(c, r + 8) << 4) + within;
            asm volatile("st.shared.b32 [%0], %1;" :: "r"(o0), "r"(*reinterpret_cast<uint32_t*>(&p0)) : "memory");
            asm volatile("st.shared.b32 [%0], %1;" :: "r"(o1), "r"(*reinterpret_cast<uint32_t*>(&p1)) : "memory");
        }
    }
    asm volatile("cp.async.wait_group 0;" ::: "memory");
    __syncthreads();

    // bucket MMA: U_tile[128,64] = EXPtile[128,128(k)] @ S[64,128(k)]^T
    // warp grid 4M x 2N: warp tile 32 rows x 32 buckets
    const int wm2 = wid & 3;            // 0..3
    const int wn2 = wid >> 2;           // 0..1
    const int a2_row0 = wm2 * 32 + (lane & 15);
    const int a2_hi   = lane >> 4;
    const int b2_n0   = wn2 * 32 + (lane & 7) + ((lane >> 4) << 3);
    const int b2_sel  = (lane >> 3) & 1;

    float4 acc2[2][4];
    #pragma unroll
    for (int mi = 0; mi < 2; mi++)
        #pragma unroll
        for (int ni = 0; ni < 4; ni++)
            acc2[mi][ni] = make_float4(0.f, 0.f, 0.f, 0.f);

    #pragma unroll
    for (int ks = 0; ks < 8; ks++) {
        uint32_t af[2][4];
        #pragma unroll
        for (int mi = 0; mi < 2; mi++) {
            int r = a2_row0 + mi * 16;
            int c = ks * 2 + a2_hi;
            ldsm4(af[mi], EB + r * 256 + (sw256(c, r) << 4));
        }
        uint32_t bf[4][2];
        #pragma unroll
        for (int nj = 0; nj < 2; nj++) {
            int n = b2_n0 + nj * 16;
            int c = ks * 2 + b2_sel;
            uint32_t t[4];
            ldsm4(t, SB + n * 256 + (sw256(c, n) << 4));
            bf[nj * 2][0]     = t[0];
            bf[nj * 2][1]     = t[1];
            bf[nj * 2 + 1][0] = t[2];
            bf[nj * 2 + 1][1] = t[3];
        }
        #pragma unroll
        for (int mi = 0; mi < 2; mi++)
            #pragma unroll
            for (int ni = 0; ni < 4; ni++)
                mma_bf16(acc2[mi][ni], af[mi], bf[ni]);
    }

    // atomic accumulate into g_U (skip padded buckets >= 48)
    #pragma unroll
    for (int mi = 0; mi < 2; mi++) {
        int R = bm * 128 + wm2 * 32 + mi * 16 + (lane >> 2);
        #pragma unroll
        for (int ni = 0; ni < 4; ni++) {
            int col = wn2 * 32 + ni * 8 + (lane & 3) * 2;
            if (col < 48) {
                float4 v = acc2[mi][ni];
                atomicAdd(&g_U[R * NBUK + col],           v.x);
                atomicAdd(&g_U[R * NBUK + col + 1],       v.y);
                atomicAdd(&g_U[(R + 8) * NBUK + col],     v.z);
                atomicAdd(&g_U[(R + 8) * NBUK + col + 1], v.w);
            }
        }
    }
}

// ---------------- finalize: out[c][b][k] = U[b][c*8+k] / Z_b ----------------
__global__ void finalize_kernel(float* __restrict__ out) {
    int b = blockIdx.x * blockDim.x + threadIdx.x;
    if (b >= B_ROWS) return;
    const float4* Urow = reinterpret_cast<const float4*>(&g_U[b * NBUK]);
    float4 u0 = Urow[0], u1 = Urow[1];
    float Z = u0.x + u0.y + u0.z + u0.w + u1.x + u1.y + u1.z + u1.w;
    float inv = 1.0f / Z;
    #pragma unroll
    for (int c = 0; c < 6; c++) {
        float4 a = Urow[c * 2], d = Urow[c * 2 + 1];
        a.x *= inv; a.y *= inv; a.z *= inv; a.w *= inv;
        d.x *= inv; d.y *= inv; d.z *= inv; d.w *= inv;
        float4* o = reinterpret_cast<float4*>(&out[c * (B_ROWS * 8) + b * 8]);
        o[0] = a;
        o[1] = d;
    }
}

// ---------------- launch ----------------
extern "C" void kernel_launch(void* const* d_in, const int* in_sizes, int n_in,
                              void* d_out, int out_size) {
    const float* E    = (const float*)d_in[0];   // [4096,1024]
    const float* W    = (const float*)d_in[1];   // [8192,1024]
    const float* bias = (const float*)d_in[2];   // [8192]
    const int*   vs   = (const int*)d_in[3];     // [8192]
    float* out = (float*)d_out;                  // [6,4096,8]

    cudaFuncSetAttribute(gemm_fused_kernel,
                         cudaFuncAttributeMaxDynamicSharedMemorySize, G1_SMEM);

    prep_kernel<<<14592, 256>>>(E, W, vs);
    gemm_fused_kernel<<<dim3(64, 32), 256, G1_SMEM>>>(bias);   // 2048 CTAs
    finalize_kernel<<<(B_ROWS + 255) / 256, 256>>>(out);
}